// round 1
// baseline (speedup 1.0000x reference)
#include <cuda_runtime.h>
#include <cstdint>
#include <math.h>

// Problem constants (fixed by the dataset)
#define BATCH 64
#define NN    1024
#define DD    16

// Kernel tiling
#define WARPS   8
#define THREADS 256
#define ROWS    64      // rows per CTA (lane handles r=lane and r=lane+32)
#define JW      128     // j-window per warp
#define JT      16      // j-tile (staged through smem)
#define NTILES  (JW / JT)
#define RP      65      // sAT pitch in floats (64 rows + 1 pad -> conflict-light)

// smem layout (floats):
//   sF   [0 .. 16384)              : F[b] (1024 x 16)
//   sAT  [16384 .. +8*JT*RP)       : per-warp transposed A tile [JT][RP]
//   sDeg [ .. +64*9)               : per-row per-warp deg partials
//   sC   [ .. +64*9)               : per-row per-warp combined partials
#define SF_FLOATS   (NN * DD)
#define SAT_FLOATS  (WARPS * JT * RP)
#define SDEG_OFF    (SF_FLOATS + SAT_FLOATS)
#define SC_OFF      (SDEG_OFF + ROWS * 9)
#define SMEM_FLOATS (SC_OFF + ROWS * 9)
#define SMEM_BYTES  (SMEM_FLOATS * 4)

// ---------------- packed f32x2 helpers (Blackwell FFMA2 path) ----------------
__device__ __forceinline__ unsigned long long pk2(float a, float b) {
    unsigned long long r;
    asm("mov.b64 %0, {%1, %2};" : "=l"(r) : "f"(a), "f"(b));
    return r;
}
__device__ __forceinline__ void upk2(unsigned long long v, float& a, float& b) {
    asm("mov.b64 {%0, %1}, %2;" : "=f"(a), "=f"(b) : "l"(v));
}
__device__ __forceinline__ unsigned long long fma2(unsigned long long a,
                                                   unsigned long long b,
                                                   unsigned long long c) {
    unsigned long long d;
    asm("fma.rn.f32x2 %0, %1, %2, %3;" : "=l"(d) : "l"(a), "l"(b), "l"(c));
    return d;
}
__device__ __forceinline__ unsigned long long add2(unsigned long long a,
                                                   unsigned long long b) {
    unsigned long long d;
    asm("add.rn.f32x2 %0, %1, %2;" : "=l"(d) : "l"(a), "l"(b));
    return d;
}

__global__ void zero_out_kernel(float* out) {
    if (threadIdx.x < BATCH) out[threadIdx.x] = 0.0f;
}

__global__ void __launch_bounds__(THREADS, 2)
graph_loss_kernel(const float* __restrict__ A,
                  const float* __restrict__ Fm,
                  float* __restrict__ out) {
    extern __shared__ float sm[];
    float* sF   = sm;
    float* sDeg = sm + SDEG_OFF;
    float* sC   = sm + SC_OFF;

    const int b    = blockIdx.y;
    const int n0   = blockIdx.x * ROWS;
    const int tid  = threadIdx.x;
    const int w    = tid >> 5;
    const int lane = tid & 31;

    // ---- load F[b] into shared (coalesced float4) ----
    {
        const float4* Fg  = (const float4*)(Fm + (size_t)b * NN * DD);
        float4*       sF4 = (float4*)sF;
        #pragma unroll
        for (int i = 0; i < (SF_FLOATS / 4) / THREADS; i++)
            sF4[tid + i * THREADS] = Fg[tid + i * THREADS];
    }
    __syncthreads();

    float* myAT = sm + SF_FLOATS + w * (JT * RP);

    // Warp's A window base: rows [n0, n0+64), cols [w*JW, w*JW+JW)
    const float* Aw = A + ((size_t)b * NN + n0) * NN + w * JW;

    const int rbase = lane >> 2;        // 0..7 (row within staging step)
    const int sub   = lane & 3;         // float4 index within a 16-float tile row
    const int jb    = sub * 4;

    // Accumulators: AF for row0 (=lane) and row1 (=lane+32), 8 f32x2 each (D=16)
    unsigned long long af0[8], af1[8];
    #pragma unroll
    for (int q = 0; q < 8; q++) { af0[q] = 0ull; af1[q] = 0ull; }
    unsigned long long deg2_0 = 0ull, ss2_0 = 0ull;
    unsigned long long deg2_1 = 0ull, ss2_1 = 0ull;

    float4 pf[8];
    // prefetch tile 0
    #pragma unroll
    for (int s = 0; s < 8; s++) {
        int r = 8 * s + rbase;
        pf[s] = *(const float4*)(Aw + (size_t)r * NN + jb);
    }

    #pragma unroll 1
    for (int t = 0; t < NTILES; t++) {
        // stage prefetched tile -> transposed smem sAT[j][r]
        #pragma unroll
        for (int s = 0; s < 8; s++) {
            int r = 8 * s + rbase;
            myAT[(jb + 0) * RP + r] = pf[s].x;
            myAT[(jb + 1) * RP + r] = pf[s].y;
            myAT[(jb + 2) * RP + r] = pf[s].z;
            myAT[(jb + 3) * RP + r] = pf[s].w;
        }
        __syncwarp();

        // prefetch next tile while computing this one
        if (t + 1 < NTILES) {
            const float* Anext = Aw + (t + 1) * JT;
            #pragma unroll
            for (int s = 0; s < 8; s++) {
                int r = 8 * s + rbase;
                pf[s] = *(const float4*)(Anext + (size_t)r * NN + jb);
            }
        }

        const int jgbase = w * JW + t * JT;   // global j of this tile's column 0
        #pragma unroll
        for (int jp = 0; jp < 8; jp++) {
            const int j0 = 2 * jp;
            // A values for 2 rows x 2 j's (conflict-free LDS.32: lane = row)
            float a00 = myAT[j0 * RP + lane];            // row0, j0
            float a01 = myAT[j0 * RP + 32 + lane];       // row1, j0
            float a10 = myAT[(j0 + 1) * RP + lane];      // row0, j1
            float a11 = myAT[(j0 + 1) * RP + 32 + lane]; // row1, j1

            // F rows (broadcast LDS.128, already packed as f32x2 pairs)
            const ulonglong2* f0p = (const ulonglong2*)&sF[(jgbase + j0) * DD];
            const ulonglong2* f1p = (const ulonglong2*)&sF[(jgbase + j0 + 1) * DD];
            ulonglong2 f0a = f0p[0], f0b = f0p[1];
            ulonglong2 f1a = f1p[0], f1b = f1p[1];

            unsigned long long A00 = pk2(a00, a00);
            unsigned long long A01 = pk2(a01, a01);
            unsigned long long A10 = pk2(a10, a10);
            unsigned long long A11 = pk2(a11, a11);

            // AF row0 += a00*F[j0] + a10*F[j1]
            af0[0] = fma2(A00, f0a.x, af0[0]);
            af0[1] = fma2(A00, f0a.y, af0[1]);
            af0[2] = fma2(A00, f0b.x, af0[2]);
            af0[3] = fma2(A00, f0b.y, af0[3]);
            af0[4] = fma2(A10, f1a.x, af0[4]);
            af0[5] = fma2(A10, f1a.y, af0[5]);
            af0[6] = fma2(A10, f1b.x, af0[6]);
            af0[7] = fma2(A10, f1b.y, af0[7]);
            // AF row1 += a01*F[j0] + a11*F[j1]
            af1[0] = fma2(A01, f0a.x, af1[0]);
            af1[1] = fma2(A01, f0a.y, af1[1]);
            af1[2] = fma2(A01, f0b.x, af1[2]);
            af1[3] = fma2(A01, f0b.y, af1[3]);
            af1[4] = fma2(A11, f1a.x, af1[4]);
            af1[5] = fma2(A11, f1a.y, af1[5]);
            af1[6] = fma2(A11, f1b.x, af1[6]);
            af1[7] = fma2(A11, f1b.y, af1[7]);

            // deg / sum(A^2), packed across the j-pair
            unsigned long long p0 = pk2(a00, a10);
            unsigned long long p1 = pk2(a01, a11);
            deg2_0 = add2(deg2_0, p0);
            ss2_0  = fma2(p0, p0, ss2_0);
            deg2_1 = add2(deg2_1, p1);
            ss2_1  = fma2(p1, p1, ss2_1);
        }
        __syncwarp();
    }

    // NOTE: af[q].x/.y hold AF[d] pairs for this warp's j-slice.
    // dot_n = sum_d AF[n,d] * f_n[d]   (partial over this warp's slice)
    const float invN2 = 1.0f / ((float)NN * (float)NN);

    // row0 = lane
    {
        const ulonglong2* fnp = (const ulonglong2*)&sF[(n0 + lane) * DD];
        ulonglong2 fna = fnp[0], fnb = fnp[1];
        unsigned long long acc = 0ull;
        acc = fma2(af0[0], fna.x, acc);
        acc = fma2(af0[1], fna.y, acc);
        acc = fma2(af0[2], fnb.x, acc);
        acc = fma2(af0[3], fnb.y, acc);
        acc = fma2(af0[4], fna.x, acc);
        acc = fma2(af0[5], fna.y, acc);
        acc = fma2(af0[6], fnb.x, acc);
        acc = fma2(af0[7], fnb.y, acc);
        float ax, ay; upk2(acc, ax, ay);
        float dot = ax + ay;
        float dA, dB; upk2(deg2_0, dA, dB);
        float deg = dA + dB;
        float sA, sB; upk2(ss2_0, sA, sB);
        float ss = sA + sB;
        sDeg[lane * 9 + w] = deg;
        sC[lane * 9 + w]   = (0.1f * ss - 0.2f * dot) * invN2;
    }
    // row1 = lane + 32
    {
        const ulonglong2* fnp = (const ulonglong2*)&sF[(n0 + 32 + lane) * DD];
        ulonglong2 fna = fnp[0], fnb = fnp[1];
        unsigned long long acc = 0ull;
        acc = fma2(af1[0], fna.x, acc);
        acc = fma2(af1[1], fna.y, acc);
        acc = fma2(af1[2], fnb.x, acc);
        acc = fma2(af1[3], fnb.y, acc);
        acc = fma2(af1[4], fna.x, acc);
        acc = fma2(af1[5], fna.y, acc);
        acc = fma2(af1[6], fnb.x, acc);
        acc = fma2(af1[7], fnb.y, acc);
        float ax, ay; upk2(acc, ax, ay);
        float dot = ax + ay;
        float dA, dB; upk2(deg2_1, dA, dB);
        float deg = dA + dB;
        float sA, sB; upk2(ss2_1, sA, sB);
        float ss = sA + sB;
        sDeg[(32 + lane) * 9 + w] = deg;
        sC[(32 + lane) * 9 + w]   = (0.1f * ss - 0.2f * dot) * invN2;
    }
    __syncthreads();

    // Final per-row combine + batch reduction (warps 0,1 cover the 64 rows)
    if (w < 2) {
        const int row = w * 32 + lane;
        float deg = 0.0f, c = 0.0f;
        #pragma unroll
        for (int k = 0; k < WARPS; k++) {
            deg += sDeg[row * 9 + k];
            c   += sC[row * 9 + k];
        }
        // ||f_n||^2
        const float* fn = &sF[(n0 + row) * DD];
        float nrm = 0.0f;
        #pragma unroll
        for (int d = 0; d < DD; d++) nrm += fn[d] * fn[d];

        float v = c + (0.2f * invN2) * deg * nrm
                    - (0.1f / (float)NN) * logf(deg + 1e-12f);

        #pragma unroll
        for (int o = 16; o > 0; o >>= 1)
            v += __shfl_down_sync(0xFFFFFFFFu, v, o);
        if (lane == 0) atomicAdd(&out[b], v);
    }
}

extern "C" void kernel_launch(void* const* d_in, const int* in_sizes, int n_in,
                              void* d_out, int out_size) {
    const float* A  = (const float*)d_in[0];   // [64,1024,1024]
    const float* Fm = (const float*)d_in[1];   // [64,1024,16]
    float* out      = (float*)d_out;           // [64]

    cudaFuncSetAttribute(graph_loss_kernel,
                         cudaFuncAttributeMaxDynamicSharedMemorySize, SMEM_BYTES);

    zero_out_kernel<<<1, 64>>>(out);

    dim3 grid(NN / ROWS, BATCH);   // (16, 64)
    graph_loss_kernel<<<grid, THREADS, SMEM_BYTES>>>(A, Fm, out);
}